// round 1
// baseline (speedup 1.0000x reference)
#include <cuda_runtime.h>
#include <cstdint>

#define Bc 32
#define Lc 4096
#define Hc 256
#define Nc 512
#define NROWS (Bc * Nc)          // 16384
#define SLOPE 0.2f
#define NCAP 1024
#define NEGINF (-3.4028234663852886e38f)

// ---------------- scratch (device globals; no allocation allowed) ----------------
__device__ float g_X[(size_t)NROWS * 512];     // node_in (asp_repr | opi_repr)
__device__ float g_node[(size_t)NROWS * 256];  // triplet-projected nodes
__device__ float g_agg[(size_t)NROWS * 512];   // [agg_node | agg_e]
__device__ float g_add[(size_t)NROWS * 256];   // node_add
__device__ float g_AT[NROWS];
__device__ float g_AS[NROWS];
__device__ float g_AE[2];
__device__ int   g_hn[NROWS];
__device__ int   g_bhas[Bc];

// ---------------- 1) span means -> node_in ----------------
__global__ __launch_bounds__(256) void spanKernel(
    const float* __restrict__ emb,
    const int* __restrict__ asp_st, const int* __restrict__ asp_len,
    const int* __restrict__ opi_st, const int* __restrict__ opi_len)
{
    int row = blockIdx.x;          // b*512 + n
    int b   = row >> 9;
    int h   = threadIdx.x;         // 0..255
    const float* e = emb + (size_t)b * Lc * Hc;

    int st = asp_st[row], ln = asp_len[row];
    float s = 0.f;
    for (int t = 0; t <= ln; t++) s += e[(size_t)(st + t) * Hc + h];
    g_X[(size_t)row * 512 + h] = s / (float)(ln + 1);

    st = opi_st[row]; ln = opi_len[row];
    s = 0.f;
    for (int t = 0; t <= ln; t++) s += e[(size_t)(st + t) * Hc + h];
    g_X[(size_t)row * 512 + 256 + h] = s / (float)(ln + 1);
}

// ---------------- 2) SGEMM 128x128x8 (MODE 0: trip proj, MODE 1: gat proj) -------
template <int MODE>
__global__ __launch_bounds__(256) void sgemmKernel(
    const float* __restrict__ W,     // [512,256] row-major (first 512 rows for trip)
    const float* __restrict__ bias,  // [256]
    const float* __restrict__ Wfull, // full W_trip (for sent rows), unused in MODE 1
    const int* __restrict__ sent)    // sent_id flat, unused in MODE 1
{
    __shared__ __align__(16) float As[8][128];
    __shared__ __align__(16) float Bs[8][128];

    const float* A = (MODE == 0) ? g_X : g_agg;
    const int K = 512;
    int tid = threadIdx.x;
    int bc  = blockIdx.x;   // 0..1  (N=256)
    int br  = blockIdx.y;   // 0..127

    int aRow = tid >> 1;           // 0..127
    int aCol = (tid & 1) * 4;      // 0 or 4
    int bRow = tid >> 5;           // 0..7
    int bCol = (tid & 31) * 4;     // 0..124

    const float* Ab = A + (size_t)(br * 128) * K;

    float acc[8][8];
#pragma unroll
    for (int i = 0; i < 8; i++)
#pragma unroll
        for (int j = 0; j < 8; j++) acc[i][j] = 0.f;

    int trow = (tid >> 4) * 8;
    int tcol = (tid & 15) * 8;

    for (int k0 = 0; k0 < K; k0 += 8) {
        float4 av = *(const float4*)(Ab + (size_t)aRow * K + k0 + aCol);
        As[aCol + 0][aRow] = av.x;
        As[aCol + 1][aRow] = av.y;
        As[aCol + 2][aRow] = av.z;
        As[aCol + 3][aRow] = av.w;
        float4 bv = *(const float4*)(W + (size_t)(k0 + bRow) * 256 + bc * 128 + bCol);
        *(float4*)&Bs[bRow][bCol] = bv;
        __syncthreads();
#pragma unroll
        for (int k = 0; k < 8; k++) {
            float a[8], bb[8];
            *(float4*)&a[0]  = *(const float4*)&As[k][trow];
            *(float4*)&a[4]  = *(const float4*)&As[k][trow + 4];
            *(float4*)&bb[0] = *(const float4*)&Bs[k][tcol];
            *(float4*)&bb[4] = *(const float4*)&Bs[k][tcol + 4];
#pragma unroll
            for (int i = 0; i < 8; i++)
#pragma unroll
                for (int j = 0; j < 8; j++) acc[i][j] += a[i] * bb[j];
        }
        __syncthreads();
    }

#pragma unroll
    for (int i = 0; i < 8; i++) {
        int r = br * 128 + trow + i;
        int sid = 0;
        if (MODE == 0) sid = sent[r];
        int bb_ = r >> 9;
#pragma unroll
        for (int j = 0; j < 8; j++) {
            int c = bc * 128 + tcol + j;
            float v = acc[i][j];
            if (MODE == 0) {
                v += bias[c] + Wfull[(size_t)(512 + sid) * 256 + c];
                g_node[(size_t)r * 256 + c] = v;
            } else {
                v += bias[c];
                v = fmaxf(v, 0.f);
                float outv;
                if (g_bhas[bb_]) outv = g_hn[r] ? v : g_node[(size_t)r * 256 + c];
                else             outv = 0.f;
                g_add[(size_t)r * 256 + c] = outv;
            }
        }
    }
}

// ---------------- 3) per-row attention scalars + a_e + zero bhas ------------------
__global__ __launch_bounds__(256) void statsKernel(
    const float* __restrict__ W_attn, const float* __restrict__ edge_emb)
{
    int row = blockIdx.x;
    int h   = threadIdx.x;
    if (row == NROWS) {
        if (h < 2) {
            float s = 0.f;
            for (int k = 0; k < 256; k++) {
                float v = edge_emb[h * 256 + k];
                v = (v >= 0.f) ? v : SLOPE * v;
                s += v * W_attn[512 + k];
            }
            g_AE[h] = s;
        }
        if (h >= 2 && h < 2 + Bc) g_bhas[h - 2] = 0;
        return;
    }
    float v  = g_node[(size_t)row * 256 + h];
    float lv = (v >= 0.f) ? v : SLOPE * v;
    float at = lv * W_attn[h];
    float as = lv * W_attn[256 + h];
#pragma unroll
    for (int o = 16; o; o >>= 1) {
        at += __shfl_xor_sync(0xffffffffu, at, o);
        as += __shfl_xor_sync(0xffffffffu, as, o);
    }
    __shared__ float sAt[8], sAs[8];
    if ((h & 31) == 0) { sAt[h >> 5] = at; sAs[h >> 5] = as; }
    __syncthreads();
    if (h == 0) {
        float a = 0.f, s2 = 0.f;
        for (int i = 0; i < 8; i++) { a += sAt[i]; s2 += sAs[i]; }
        g_AT[row] = a;
        g_AS[row] = s2;
    }
}

// ---------------- 4) sparse edge discovery + softmax + aggregation ----------------
__global__ __launch_bounds__(256) void edgeKernel(
    const int* __restrict__ asp_st, const int* __restrict__ asp_len,
    const int* __restrict__ opi_st, const int* __restrict__ opi_len,
    const float* __restrict__ edge_emb, const float* __restrict__ b_attn)
{
    int row = blockIdx.x;
    int b   = row >> 9;
    int t   = row & 511;
    int tid = threadIdx.x;
    int base = b * Nc;

    __shared__ float nodeT[256];
    __shared__ int   cnt[257];
    __shared__ int   cand[NCAP];
    __shared__ float sc[NCAP];
    __shared__ int   s_m2;
    __shared__ float s_den, s_w0, s_w1;

    nodeT[tid] = g_node[(size_t)row * 256 + tid];
    if (tid == 0) s_m2 = 0;

    int ast = asp_st[base + t], aln = asp_len[base + t];
    int ost = opi_st[base + t], oln = opi_len[base + t];

    int myc[4];
    int nmy = 0;
#pragma unroll
    for (int j = 0; j < 2; j++) {
        int s = 2 * tid + j;
        bool na = (s != t) && (asp_st[base + s] == ast) && (asp_len[base + s] == aln);
        bool no = (s != t) && (opi_st[base + s] == ost) && (opi_len[base + s] == oln);
        if (na) myc[nmy++] = s;                 // type 0
        if (no) myc[nmy++] = s | (1 << 16);     // type 1
    }
    cnt[tid] = nmy;
    __syncthreads();
    if (tid == 0) {                              // serial exclusive scan (deterministic)
        int run = 0;
        for (int i = 0; i < 256; i++) { int c = cnt[i]; cnt[i] = run; run += c; }
        cnt[256] = run;
    }
    __syncthreads();
    int pos = cnt[tid];
    for (int i = 0; i < nmy; i++) cand[pos + i] = myc[i];
    __syncthreads();

    int m1 = cnt[256];
    float atv   = g_AT[row];
    float battn = b_attn[0];

    int warp = tid >> 5, lane = tid & 31;
    for (int e = warp; e < m1; e += 8) {
        int cd = cand[e];
        int s  = cd & 0xffff;
        int ty = cd >> 16;
        const float* ns = g_node + (size_t)(base + s) * 256;
        float d = 0.f;
#pragma unroll
        for (int k = 0; k < 8; k++) d += nodeT[lane + 32 * k] * ns[lane + 32 * k];
#pragma unroll
        for (int o = 16; o; o >>= 1) d += __shfl_xor_sync(0xffffffffu, d, o);
        if (lane == 0) {
            if (d > 0.f) {
                sc[e] = atv + g_AS[base + s] + g_AE[ty] + battn;
                atomicAdd(&s_m2, 1);
            } else {
                sc[e] = NEGINF;
            }
        }
    }
    __syncthreads();

    int m2 = s_m2;
    if (tid == 0 && m2 > 0) {
        float mx = NEGINF;
        for (int e = 0; e < m1; e++) mx = fmaxf(mx, sc[e]);
        float den = 0.f, w0 = 0.f, w1 = 0.f;
        for (int e = 0; e < m1; e++) {
            float we = expf(sc[e] - mx);     // rejected: expf(-huge) == 0 exactly
            sc[e] = we;
            den += we;
            if ((cand[e] >> 16) == 0) w0 += we; else w1 += we;
        }
        s_den = den;
        s_w0  = w0 / den;
        s_w1  = w1 / den;
    }
    __syncthreads();

    size_t arow = (size_t)row * 512;
    if (m2 > 0) {
        float inv = 1.0f / s_den;
        float an = 0.f;
        for (int e = 0; e < m1; e++) {
            float we = sc[e];
            if (we != 0.f) {
                int s = cand[e] & 0xffff;
                an += we * g_node[(size_t)(base + s) * 256 + tid];
            }
        }
        g_agg[arow + tid]       = an * inv;
        g_agg[arow + 256 + tid] = s_w0 * edge_emb[tid] + s_w1 * edge_emb[256 + tid];
    } else {
        g_agg[arow + tid]       = 0.f;
        g_agg[arow + 256 + tid] = 0.f;
    }
    if (tid == 0) {
        g_hn[row] = (m2 > 0) ? 1 : 0;
        if (m2 > 0) atomicOr(&g_bhas[b], 1);
    }
}

// ---------------- 5) deterministic scatter-add into output ------------------------
__global__ __launch_bounds__(256) void scatterKernel(
    float* __restrict__ out,
    const int* __restrict__ asp_st, const int* __restrict__ opi_st)
{
    int b = blockIdx.x >> 7;
    int c = blockIdx.x & 127;      // centers are in [0,127]
    int h = threadIdx.x;
    __shared__ int cen[512];
    for (int i = h; i < 512; i += 256)
        cen[i] = (asp_st[b * Nc + i] + opi_st[b * Nc + i]) >> 1;
    __syncthreads();
    float s = 0.f;
    bool any = false;
    for (int n = 0; n < 512; n++) {
        if (cen[n] == c) {
            s += g_add[((size_t)(b * Nc + n)) * 256 + h];
            any = true;
        }
    }
    if (any) out[((size_t)b * Lc + c) * Hc + h] += s;
}

// ---------------- launch ----------------------------------------------------------
extern "C" void kernel_launch(void* const* d_in, const int* in_sizes, int n_in,
                              void* d_out, int out_size)
{
    const float* emb     = (const float*)d_in[0];
    const float* W_trip  = (const float*)d_in[1];
    const float* b_trip  = (const float*)d_in[2];
    const float* edge_e  = (const float*)d_in[3];
    const float* W_attn  = (const float*)d_in[4];
    const float* b_attn  = (const float*)d_in[5];
    const float* W_gat   = (const float*)d_in[6];
    const float* b_gat   = (const float*)d_in[7];
    const int*   asp_st  = (const int*)d_in[8];
    const int*   asp_len = (const int*)d_in[9];
    const int*   opi_st  = (const int*)d_in[10];
    const int*   opi_len = (const int*)d_in[11];
    const int*   sent_id = (const int*)d_in[12];
    float* out = (float*)d_out;

    // base copy of embeddings into output
    cudaMemcpyAsync(out, emb, (size_t)Bc * Lc * Hc * sizeof(float),
                    cudaMemcpyDeviceToDevice, 0);

    spanKernel<<<NROWS, 256>>>(emb, asp_st, asp_len, opi_st, opi_len);
    sgemmKernel<0><<<dim3(2, 128), 256>>>(W_trip, b_trip, W_trip, sent_id);
    statsKernel<<<NROWS + 1, 256>>>(W_attn, edge_e);
    edgeKernel<<<NROWS, 256>>>(asp_st, asp_len, opi_st, opi_len, edge_e, b_attn);
    sgemmKernel<1><<<dim3(2, 128), 256>>>(W_gat, b_gat, nullptr, nullptr);
    scatterKernel<<<Bc * 128, 256>>>(out, asp_st, opi_st);
}

// round 2
// speedup vs baseline: 1.1641x; 1.1641x over previous
#include <cuda_runtime.h>
#include <cstdint>

#define Bc 32
#define Lc 4096
#define Hc 256
#define Nc 512
#define NROWS (Bc * Nc)          // 16384
#define TT 136                   // tokens reachable by spans (st<128, len<8 -> ed<=134)
#define PROWS (Bc * TT)          // 4352
#define SLOPE 0.2f
#define NEGINF (-3.4028234663852886e38f)
#define EDGECAP (Nc * (Nc - 1) * 2)   // worst-case edges per batch

typedef unsigned long long u64;

// ---------------- scratch (device globals) ----------------
__device__ float g_Y[(size_t)PROWS * 512];            // projected tokens [asp|opi]
__device__ float g_PS[(size_t)Bc * (TT + 1) * 512];   // prefix sums of g_Y over t
__device__ float g_node[(size_t)NROWS * 256];
__device__ float g_agg[(size_t)NROWS * 256];          // agg_node only
__device__ float g_add[(size_t)NROWS * 256];
__device__ float g_AT[NROWS];
__device__ float g_AS[NROWS];
__device__ float g_AE[2];
__device__ float g_E[2][256];                          // edge_emb @ W_gat[256:512]
__device__ float g_w0[NROWS];
__device__ float g_w1[NROWS];
__device__ int   g_hn[NROWS];
__device__ int   g_bhas[Bc];
__device__ int   g_rowcnt[NROWS];
__device__ int   g_rowoff[NROWS];
__device__ int   g_cand[(size_t)Bc * EDGECAP];

// ---------------- f32x2 helpers (sm_100+) ----------------
__device__ __forceinline__ u64 bcast2(float x) {
    u64 r; unsigned xi = __float_as_uint(x);
    asm("mov.b64 %0, {%1, %1};" : "=l"(r) : "r"(xi));
    return r;
}
__device__ __forceinline__ void ffma2(u64& d, u64 a, u64 b) {
    asm("fma.rn.f32x2 %0, %1, %2, %0;" : "+l"(d) : "l"(a), "l"(b));
}
__device__ __forceinline__ float2 unpk2(u64 v) {
    float2 r;
    asm("mov.b64 {%0, %1}, %2;" : "=f"(r.x), "=f"(r.y) : "l"(v));
    return r;
}

// ---------------- GEMM 128x128x8 with FFMA2 ----------------
// MODE 0: Y = emb_tokens[4352,256] @ Wcat[256,512]   grid(4, 34)
// MODE 1: upd = g_agg[16384,256] @ W_gat[0:256,256]  grid(2, 128) + epilogue
template <int MODE>
__global__ __launch_bounds__(256) void gemmKernel(
    const float* __restrict__ Aemb,
    const float* __restrict__ W,
    const float* __restrict__ bias)
{
    __shared__ __align__(16) float As[8][128];
    __shared__ __align__(16) float Bs[8][128];
    int tid = threadIdx.x, bc = blockIdx.x, br = blockIdx.y;
    int aRow = tid >> 1, aCol = (tid & 1) * 4;
    int bRow = tid >> 5, bCol = (tid & 31) * 4;

    const float* Aptr;
    if (MODE == 0) {
        int r = br * 128 + aRow;
        int b = r / TT;
        int t = r - b * TT;
        Aptr = Aemb + ((size_t)(b * Lc + t)) * 256 + aCol;
    } else {
        Aptr = g_agg + (size_t)(br * 128 + aRow) * 256 + aCol;
    }
    const float* Bptr;
    {
        int j = bc * 128 + bCol;
        if (MODE == 0) {
            int half = (j >= 256);
            Bptr = W + (size_t)(half * 256 + bRow) * 256 + (j & 255);
        } else {
            Bptr = W + (size_t)bRow * 256 + j;
        }
    }

    u64 acc2[4][8];
#pragma unroll
    for (int i = 0; i < 4; i++)
#pragma unroll
        for (int j = 0; j < 8; j++) acc2[i][j] = 0ull;

    int trow = (tid >> 4) * 8;   // even -> 8B-aligned LDS.64 reads
    int tcol = (tid & 15) * 8;

    for (int k0 = 0; k0 < 256; k0 += 8) {
        float4 av = *(const float4*)(Aptr + k0);
        As[aCol + 0][aRow] = av.x;
        As[aCol + 1][aRow] = av.y;
        As[aCol + 2][aRow] = av.z;
        As[aCol + 3][aRow] = av.w;
        float4 bv = *(const float4*)(Bptr + (size_t)k0 * 256);
        *(float4*)&Bs[bRow][bCol] = bv;
        __syncthreads();
#pragma unroll
        for (int k = 0; k < 8; k++) {
            const u64* a64 = (const u64*)&As[k][trow];
            u64 a2[4] = { a64[0], a64[1], a64[2], a64[3] };
            float bb[8];
            *(float4*)&bb[0] = *(const float4*)&Bs[k][tcol];
            *(float4*)&bb[4] = *(const float4*)&Bs[k][tcol + 4];
            u64 b2[8];
#pragma unroll
            for (int j = 0; j < 8; j++) b2[j] = bcast2(bb[j]);
#pragma unroll
            for (int i = 0; i < 4; i++)
#pragma unroll
                for (int j = 0; j < 8; j++) ffma2(acc2[i][j], a2[i], b2[j]);
        }
        __syncthreads();
    }

    if (MODE == 0) {
#pragma unroll
        for (int i2 = 0; i2 < 4; i2++) {
            int r0 = br * 128 + trow + 2 * i2;
#pragma unroll
            for (int j = 0; j < 8; j++) {
                float2 v = unpk2(acc2[i2][j]);
                int c = bc * 128 + tcol + j;
                g_Y[(size_t)r0 * 512 + c]       = v.x;
                g_Y[(size_t)(r0 + 1) * 512 + c] = v.y;
            }
        }
    } else {
#pragma unroll
        for (int i2 = 0; i2 < 4; i2++) {
            int r0 = br * 128 + trow + 2 * i2;
#pragma unroll
            for (int half = 0; half < 2; half++) {
                int r = r0 + half;
                int bb_ = r >> 9;
                float w0 = g_w0[r], w1 = g_w1[r];
                int hn = g_hn[r], bh = g_bhas[bb_];
#pragma unroll
                for (int j = 0; j < 8; j++) {
                    float2 v = unpk2(acc2[i2][j]);
                    float val = half ? v.y : v.x;
                    int c = bc * 128 + tcol + j;
                    float u = val + bias[c] + w0 * g_E[0][c] + w1 * g_E[1][c];
                    u = fmaxf(u, 0.f);
                    float outv = bh ? (hn ? u : g_node[(size_t)r * 256 + c]) : 0.f;
                    g_add[(size_t)r * 256 + c] = outv;
                }
            }
        }
    }
}

// ---------------- prefix sums over t ----------------
__global__ __launch_bounds__(512) void prefixKernel()
{
    int b = blockIdx.x, j = threadIdx.x;
    const float* Y = g_Y + (size_t)b * TT * 512 + j;
    float* PS = g_PS + (size_t)b * (TT + 1) * 512 + j;
    float run = 0.f;
    PS[0] = 0.f;
#pragma unroll 4
    for (int t = 0; t < TT; t++) {
        run += Y[(size_t)t * 512];
        PS[(size_t)(t + 1) * 512] = run;
    }
}

// ---------------- node = span means of projected tokens + sent row + bias ------
__global__ __launch_bounds__(256) void nodeKernel(
    const int* __restrict__ asp_st, const int* __restrict__ asp_len,
    const int* __restrict__ opi_st, const int* __restrict__ opi_len,
    const int* __restrict__ sent, const float* __restrict__ W_trip,
    const float* __restrict__ b_trip)
{
    int row = blockIdx.x, b = row >> 9, h = threadIdx.x;
    const float* PS = g_PS + (size_t)b * (TT + 1) * 512;
    int ast = asp_st[row], aln = asp_len[row];
    int ost = opi_st[row], oln = opi_len[row];
    float av = (PS[(size_t)(ast + aln + 1) * 512 + h] - PS[(size_t)ast * 512 + h])
               / (float)(aln + 1);
    float ov = (PS[(size_t)(ost + oln + 1) * 512 + 256 + h] - PS[(size_t)ost * 512 + 256 + h])
               / (float)(oln + 1);
    int sid = sent[row];
    g_node[(size_t)row * 256 + h] = av + ov + W_trip[(size_t)(512 + sid) * 256 + h] + b_trip[h];
}

// ---------------- per-row attention scalars, a_e, e_g, bhas reset --------------
__global__ __launch_bounds__(256) void statsKernel(
    const float* __restrict__ W_attn, const float* __restrict__ edge_emb,
    const float* __restrict__ W_gat)
{
    int row = blockIdx.x;
    int h = threadIdx.x;
    if (row >= NROWS) {
        int which = row - NROWS;
        if (which == 0) {
            if (h < 2) {
                float s = 0.f;
                for (int k = 0; k < 256; k++) {
                    float v = edge_emb[h * 256 + k];
                    v = (v >= 0.f) ? v : SLOPE * v;
                    s += v * W_attn[512 + k];
                }
                g_AE[h] = s;
            }
            if (h >= 2 && h < 2 + Bc) g_bhas[h - 2] = 0;
        } else {
            int e = which - 1;   // 0 or 1
            float s = 0.f;
            for (int k = 0; k < 256; k++)
                s += edge_emb[e * 256 + k] * W_gat[(size_t)(256 + k) * 256 + h];
            g_E[e][h] = s;
        }
        return;
    }
    float v = g_node[(size_t)row * 256 + h];
    float lv = (v >= 0.f) ? v : SLOPE * v;
    float at = lv * W_attn[h];
    float as = lv * W_attn[256 + h];
#pragma unroll
    for (int o = 16; o; o >>= 1) {
        at += __shfl_xor_sync(0xffffffffu, at, o);
        as += __shfl_xor_sync(0xffffffffu, as, o);
    }
    __shared__ float sAt[8], sAs[8];
    if ((h & 31) == 0) { sAt[h >> 5] = at; sAs[h >> 5] = as; }
    __syncthreads();
    if (h == 0) {
        float a = 0.f, s2 = 0.f;
        for (int i = 0; i < 8; i++) { a += sAt[i]; s2 += sAs[i]; }
        g_AT[row] = a;
        g_AS[row] = s2;
    }
}

// ---------------- per-batch CSR candidate build (deterministic) ---------------
__global__ __launch_bounds__(512) void buildKernel(
    const int* __restrict__ asp_st, const int* __restrict__ asp_len,
    const int* __restrict__ opi_st, const int* __restrict__ opi_len)
{
    int b = blockIdx.x, t = threadIdx.x;
    __shared__ int ka[512], ko[512];
    __shared__ int wsum[16];
    int base = b * Nc;
    ka[t] = asp_st[base + t] | (asp_len[base + t] << 16);
    ko[t] = opi_st[base + t] | (opi_len[base + t] << 16);
    __syncthreads();
    int mka = ka[t], mko = ko[t];
    int cnt = 0;
    for (int s = 0; s < Nc; s++) {
        if (s != t) cnt += (ka[s] == mka) + (ko[s] == mko);
    }
    // deterministic block exclusive scan
    int lane = t & 31, w = t >> 5;
    int v = cnt;
#pragma unroll
    for (int o = 1; o < 32; o <<= 1) {
        int n = __shfl_up_sync(0xffffffffu, v, o);
        if (lane >= o) v += n;
    }
    if (lane == 31) wsum[w] = v;
    __syncthreads();
    if (t == 0) {
        int run = 0;
        for (int i = 0; i < 16; i++) { int x = wsum[i]; wsum[i] = run; run += x; }
    }
    __syncthreads();
    int off = v - cnt + wsum[w];
    g_rowcnt[base + t] = cnt;
    int goff = b * EDGECAP + off;
    g_rowoff[base + t] = goff;
    int p = goff;
    for (int s = 0; s < Nc; s++) {
        if (s == t) continue;
        if (ka[s] == mka) g_cand[p++] = s;              // type 0
        if (ko[s] == mko) g_cand[p++] = s | (1 << 16);  // type 1
    }
}

// ---------------- sparse sim + softmax + node aggregation --------------------
__global__ __launch_bounds__(256) void edgeKernel(const float* __restrict__ b_attn)
{
    int row = blockIdx.x, b = row >> 9, tid = threadIdx.x;
    int m1 = g_rowcnt[row];
    if (m1 == 0) {
        if (tid == 0) g_hn[row] = 0;
        return;
    }
    int off = g_rowoff[row];
    __shared__ float nodeT[256];
    __shared__ int   cand[1024];
    __shared__ float sc[1024];
    __shared__ int   s_m2;
    __shared__ float s_inv;
    nodeT[tid] = g_node[(size_t)row * 256 + tid];
    for (int e = tid; e < m1; e += 256) cand[e] = g_cand[off + e];
    if (tid == 0) s_m2 = 0;
    __syncthreads();

    int base = b * Nc;
    float atv = g_AT[row], bat = b_attn[0];
    int warp = tid >> 5, lane = tid & 31;
    for (int e = warp; e < m1; e += 8) {
        int cd = cand[e];
        int s = cd & 0xffff, ty = cd >> 16;
        const float* ns = g_node + (size_t)(base + s) * 256;
        float d = 0.f;
#pragma unroll
        for (int k = 0; k < 8; k++) d += nodeT[lane + 32 * k] * ns[lane + 32 * k];
#pragma unroll
        for (int o = 16; o; o >>= 1) d += __shfl_xor_sync(0xffffffffu, d, o);
        if (lane == 0) {
            if (d > 0.f) {
                sc[e] = atv + g_AS[base + s] + g_AE[ty] + bat;
                atomicAdd(&s_m2, 1);
            } else {
                sc[e] = NEGINF;
            }
        }
    }
    __syncthreads();
    int m2 = s_m2;
    if (tid == 0) {
        g_hn[row] = (m2 > 0) ? 1 : 0;
        if (m2 > 0) {
            atomicOr(&g_bhas[b], 1);
            float mx = NEGINF;
            for (int e = 0; e < m1; e++) mx = fmaxf(mx, sc[e]);
            float den = 0.f, w0 = 0.f, w1 = 0.f;
            for (int e = 0; e < m1; e++) {
                float we = expf(sc[e] - mx);   // rejected -> exp(-huge) == 0 exactly
                sc[e] = we;
                den += we;
                if ((cand[e] >> 16) == 0) w0 += we; else w1 += we;
            }
            s_inv = 1.f / den;
            g_w0[row] = w0 / den;
            g_w1[row] = w1 / den;
        }
    }
    __syncthreads();
    if (m2 > 0) {
        float inv = s_inv;
        float an = 0.f;
        for (int e = 0; e < m1; e++) {
            float we = sc[e];
            if (we != 0.f) {
                int s = cand[e] & 0xffff;
                an += we * g_node[(size_t)(base + s) * 256 + tid];
            }
        }
        g_agg[(size_t)row * 256 + tid] = an * inv;
    }
}

// ---------------- deterministic scatter-add into output ----------------------
__global__ __launch_bounds__(256) void scatterKernel(
    float* __restrict__ out,
    const int* __restrict__ asp_st, const int* __restrict__ opi_st)
{
    int b = blockIdx.x >> 7;
    int c = blockIdx.x & 127;
    int h = threadIdx.x;
    __shared__ int cen[512];
    for (int i = h; i < 512; i += 256)
        cen[i] = (asp_st[b * Nc + i] + opi_st[b * Nc + i]) >> 1;
    __syncthreads();
    float s = 0.f;
    bool any = false;
    for (int n = 0; n < 512; n++) {
        if (cen[n] == c) {
            s += g_add[((size_t)(b * Nc + n)) * 256 + h];
            any = true;
        }
    }
    if (any) out[((size_t)b * Lc + c) * Hc + h] += s;
}

// ---------------- launch -----------------------------------------------------
extern "C" void kernel_launch(void* const* d_in, const int* in_sizes, int n_in,
                              void* d_out, int out_size)
{
    const float* emb     = (const float*)d_in[0];
    const float* W_trip  = (const float*)d_in[1];
    const float* b_trip  = (const float*)d_in[2];
    const float* edge_e  = (const float*)d_in[3];
    const float* W_attn  = (const float*)d_in[4];
    const float* b_attn  = (const float*)d_in[5];
    const float* W_gat   = (const float*)d_in[6];
    const float* b_gat   = (const float*)d_in[7];
    const int*   asp_st  = (const int*)d_in[8];
    const int*   asp_len = (const int*)d_in[9];
    const int*   opi_st  = (const int*)d_in[10];
    const int*   opi_len = (const int*)d_in[11];
    const int*   sent_id = (const int*)d_in[12];
    float* out = (float*)d_out;

    cudaMemcpyAsync(out, emb, (size_t)Bc * Lc * Hc * sizeof(float),
                    cudaMemcpyDeviceToDevice, 0);

    gemmKernel<0><<<dim3(4, 34), 256>>>(emb, W_trip, b_trip);
    prefixKernel<<<Bc, 512>>>();
    nodeKernel<<<NROWS, 256>>>(asp_st, asp_len, opi_st, opi_len, sent_id, W_trip, b_trip);
    statsKernel<<<NROWS + 3, 256>>>(W_attn, edge_e, W_gat);
    buildKernel<<<Bc, 512>>>(asp_st, asp_len, opi_st, opi_len);
    edgeKernel<<<NROWS, 256>>>(b_attn);
    gemmKernel<1><<<dim3(2, 128), 256>>>(nullptr, W_gat, b_gat);
    scatterKernel<<<Bc * 128, 256>>>(out, asp_st, opi_st);
}

// round 3
// speedup vs baseline: 1.2883x; 1.1067x over previous
#include <cuda_runtime.h>
#include <cstdint>

#define Bc 32
#define Lc 4096
#define Hc 256
#define Nc 512
#define NROWS (Bc * Nc)          // 16384
#define TT 136                   // tokens reachable by spans (st<128, len<8 -> ed<=134)
#define PROWS (Bc * TT)          // 4352
#define SLOPE 0.2f
#define NEGINF (-3.4028234663852886e38f)
#define EDGECAP (Nc * (Nc - 1) * 2)

typedef unsigned long long u64;

// ---------------- scratch (device globals) ----------------
__device__ float g_Y[(size_t)PROWS * 512];            // projected tokens [asp|opi]
__device__ float g_node[(size_t)NROWS * 256];
__device__ float g_agg[(size_t)NROWS * 256];
__device__ float g_add[(size_t)NROWS * 256];          // upd for active rows only
__device__ float g_AT[NROWS];
__device__ float g_AS[NROWS];
__device__ float g_AE[2];
__device__ float g_E[2][256];                          // edge_emb @ W_gat[256:512]
__device__ float g_w0[NROWS];
__device__ float g_w1[NROWS];
__device__ int   g_hn[NROWS];
__device__ int   g_bhas[Bc];
__device__ int   g_rowcnt[NROWS];
__device__ int   g_rowoff[NROWS];
__device__ int   g_cand[(size_t)Bc * EDGECAP];
__device__ int   g_rows[NROWS];                        // compacted active rows
__device__ int   g_nact;

// ---------------- f32x2 helpers (sm_100+) ----------------
__device__ __forceinline__ u64 bcast2(float x) {
    u64 r; unsigned xi = __float_as_uint(x);
    asm("mov.b64 %0, {%1, %1};" : "=l"(r) : "r"(xi));
    return r;
}
__device__ __forceinline__ void ffma2(u64& d, u64 a, u64 b) {
    asm("fma.rn.f32x2 %0, %1, %2, %0;" : "+l"(d) : "l"(a), "l"(b));
}
__device__ __forceinline__ float2 unpk2(u64 v) {
    float2 r;
    asm("mov.b64 {%0, %1}, %2;" : "=f"(r.x), "=f"(r.y) : "l"(v));
    return r;
}

// ---------------- GEMM0: Y = emb_tokens[4352,256] @ Wcat[256,512]  grid(4,34) ----
__global__ __launch_bounds__(256) void gemm0Kernel(
    const float* __restrict__ Aemb, const float* __restrict__ W)
{
    __shared__ __align__(16) float As[8][128];
    __shared__ __align__(16) float Bs[8][128];
    int tid = threadIdx.x, bc = blockIdx.x, br = blockIdx.y;
    int aRow = tid >> 1, aCol = (tid & 1) * 4;
    int bRow = tid >> 5, bCol = (tid & 31) * 4;

    int r = br * 128 + aRow;
    int b = r / TT;
    int t = r - b * TT;
    const float* Aptr = Aemb + ((size_t)(b * Lc + t)) * 256 + aCol;

    int j = bc * 128 + bCol;
    int half = (j >= 256);
    const float* Bptr = W + (size_t)(half * 256 + bRow) * 256 + (j & 255);

    u64 acc2[4][8];
#pragma unroll
    for (int i = 0; i < 4; i++)
#pragma unroll
        for (int jj = 0; jj < 8; jj++) acc2[i][jj] = 0ull;

    int trow = (tid >> 4) * 8;
    int tcol = (tid & 15) * 8;

    for (int k0 = 0; k0 < 256; k0 += 8) {
        float4 av = *(const float4*)(Aptr + k0);
        As[aCol + 0][aRow] = av.x;
        As[aCol + 1][aRow] = av.y;
        As[aCol + 2][aRow] = av.z;
        As[aCol + 3][aRow] = av.w;
        float4 bv = *(const float4*)(Bptr + (size_t)k0 * 256);
        *(float4*)&Bs[bRow][bCol] = bv;
        __syncthreads();
#pragma unroll
        for (int k = 0; k < 8; k++) {
            const u64* a64 = (const u64*)&As[k][trow];
            u64 a2[4] = { a64[0], a64[1], a64[2], a64[3] };
            float bb[8];
            *(float4*)&bb[0] = *(const float4*)&Bs[k][tcol];
            *(float4*)&bb[4] = *(const float4*)&Bs[k][tcol + 4];
            u64 b2[8];
#pragma unroll
            for (int jj = 0; jj < 8; jj++) b2[jj] = bcast2(bb[jj]);
#pragma unroll
            for (int i = 0; i < 4; i++)
#pragma unroll
                for (int jj = 0; jj < 8; jj++) ffma2(acc2[i][jj], a2[i], b2[jj]);
        }
        __syncthreads();
    }
#pragma unroll
    for (int i2 = 0; i2 < 4; i2++) {
        int r0 = br * 128 + trow + 2 * i2;
#pragma unroll
        for (int jj = 0; jj < 8; jj++) {
            float2 v = unpk2(acc2[i2][jj]);
            int c = bc * 128 + tcol + jj;
            g_Y[(size_t)r0 * 512 + c]       = v.x;
            g_Y[(size_t)(r0 + 1) * 512 + c] = v.y;
        }
    }
}

// ---------------- build: candidates CSR + misc scalars ----------------
__global__ __launch_bounds__(512) void buildKernel(
    const int* __restrict__ asp_st, const int* __restrict__ asp_len,
    const int* __restrict__ opi_st, const int* __restrict__ opi_len,
    const float* __restrict__ edge_emb, const float* __restrict__ W_attn,
    const float* __restrict__ W_gat)
{
    int b = blockIdx.x, t = threadIdx.x;
    __shared__ int ka[512], ko[512];
    __shared__ int wsum[16];
    int base = b * Nc;
    ka[t] = asp_st[base + t] | (asp_len[base + t] << 16);
    ko[t] = opi_st[base + t] | (opi_len[base + t] << 16);
    __syncthreads();
    int mka = ka[t], mko = ko[t];
    int cnt = 0;
    for (int s = 0; s < Nc; s++)
        if (s != t) cnt += (ka[s] == mka) + (ko[s] == mko);
    int lane = t & 31, w = t >> 5;
    int v = cnt;
#pragma unroll
    for (int o = 1; o < 32; o <<= 1) {
        int n = __shfl_up_sync(0xffffffffu, v, o);
        if (lane >= o) v += n;
    }
    if (lane == 31) wsum[w] = v;
    __syncthreads();
    if (t == 0) {
        int run = 0;
        for (int i = 0; i < 16; i++) { int x = wsum[i]; wsum[i] = run; run += x; }
    }
    __syncthreads();
    int off = v - cnt + wsum[w];
    g_rowcnt[base + t] = cnt;
    int p = b * EDGECAP + off;
    g_rowoff[base + t] = p;
    for (int s = 0; s < Nc; s++) {
        if (s == t) continue;
        if (ka[s] == mka) g_cand[p++] = s;
        if (ko[s] == mko) g_cand[p++] = s | (1 << 16);
    }

    // misc scalars on block 0 (independent of the above)
    if (b == 0) {
        // g_E[e][h]: t -> (e = t>>8, h = t&255)
        int e = t >> 8, h = t & 255;
        float s = 0.f;
        for (int k = 0; k < 256; k++)
            s += edge_emb[e * 256 + k] * W_gat[(size_t)(256 + k) * 256 + h];
        g_E[e][h] = s;
        if (t < 2) {
            float sa = 0.f;
            for (int k = 0; k < 256; k++) {
                float vv = edge_emb[t * 256 + k];
                vv = (vv >= 0.f) ? vv : SLOPE * vv;
                sa += vv * W_attn[512 + k];
            }
            g_AE[t] = sa;
        }
        if (t >= 4 && t < 4 + Bc) g_bhas[t - 4] = 0;
        if (t == 2) g_nact = 0;
    }
}

// ---------------- fused node + attention stats ----------------
__global__ __launch_bounds__(256) void nodeStatsKernel(
    const int* __restrict__ asp_st, const int* __restrict__ asp_len,
    const int* __restrict__ opi_st, const int* __restrict__ opi_len,
    const int* __restrict__ sent, const float* __restrict__ W_trip,
    const float* __restrict__ b_trip, const float* __restrict__ W_attn)
{
    int row = blockIdx.x, b = row >> 9, h = threadIdx.x;
    const float* Yb = g_Y + (size_t)b * TT * 512;
    int ast = asp_st[row], aln = asp_len[row];
    int ost = opi_st[row], oln = opi_len[row];

    float asum = 0.f;
    for (int k = 0; k <= aln; k++) asum += Yb[(size_t)(ast + k) * 512 + h];
    float osum = 0.f;
    for (int k = 0; k <= oln; k++) osum += Yb[(size_t)(ost + k) * 512 + 256 + h];

    int sid = sent[row];
    float v = asum / (float)(aln + 1) + osum / (float)(oln + 1)
            + W_trip[(size_t)(512 + sid) * 256 + h] + b_trip[h];
    g_node[(size_t)row * 256 + h] = v;

    float lv = (v >= 0.f) ? v : SLOPE * v;
    float at = lv * W_attn[h];
    float as = lv * W_attn[256 + h];
#pragma unroll
    for (int o = 16; o; o >>= 1) {
        at += __shfl_xor_sync(0xffffffffu, at, o);
        as += __shfl_xor_sync(0xffffffffu, as, o);
    }
    __shared__ float sAt[8], sAs[8];
    if ((h & 31) == 0) { sAt[h >> 5] = at; sAs[h >> 5] = as; }
    __syncthreads();
    if (h == 0) {
        float a = 0.f, s2 = 0.f;
#pragma unroll
        for (int i = 0; i < 8; i++) { a += sAt[i]; s2 += sAs[i]; }
        g_AT[row] = a;
        g_AS[row] = s2;
    }
}

// ---------------- sparse sim + softmax + aggregation + compaction -------------
__global__ __launch_bounds__(256) void edgeKernel(const float* __restrict__ b_attn)
{
    int row = blockIdx.x, b = row >> 9, tid = threadIdx.x;
    int m1 = g_rowcnt[row];
    if (m1 == 0) {
        if (tid == 0) g_hn[row] = 0;
        return;
    }
    int off = g_rowoff[row];
    __shared__ float nodeT[256];
    __shared__ int   cand[1024];
    __shared__ float sc[1024];
    __shared__ int   s_m2;
    __shared__ float s_inv;
    nodeT[tid] = g_node[(size_t)row * 256 + tid];
    for (int e = tid; e < m1; e += 256) cand[e] = g_cand[off + e];
    if (tid == 0) s_m2 = 0;
    __syncthreads();

    int base = b * Nc;
    float atv = g_AT[row], bat = b_attn[0];
    int warp = tid >> 5, lane = tid & 31;
    for (int e = warp; e < m1; e += 8) {
        int cd = cand[e];
        int s = cd & 0xffff, ty = cd >> 16;
        const float* ns = g_node + (size_t)(base + s) * 256;
        float d = 0.f;
#pragma unroll
        for (int k = 0; k < 8; k++) d += nodeT[lane + 32 * k] * ns[lane + 32 * k];
#pragma unroll
        for (int o = 16; o; o >>= 1) d += __shfl_xor_sync(0xffffffffu, d, o);
        if (lane == 0) {
            if (d > 0.f) {
                sc[e] = atv + g_AS[base + s] + g_AE[ty] + bat;
                atomicAdd(&s_m2, 1);
            } else {
                sc[e] = NEGINF;
            }
        }
    }
    __syncthreads();
    int m2 = s_m2;
    if (tid == 0) {
        g_hn[row] = (m2 > 0) ? 1 : 0;
        if (m2 > 0) {
            atomicOr(&g_bhas[b], 1);
            int p = atomicAdd(&g_nact, 1);
            g_rows[p] = row;
            float mx = NEGINF;
            for (int e = 0; e < m1; e++) mx = fmaxf(mx, sc[e]);
            float den = 0.f, w0 = 0.f, w1 = 0.f;
            for (int e = 0; e < m1; e++) {
                float we = expf(sc[e] - mx);
                sc[e] = we;
                den += we;
                if ((cand[e] >> 16) == 0) w0 += we; else w1 += we;
            }
            s_inv = 1.f / den;
            g_w0[row] = w0 / den;
            g_w1[row] = w1 / den;
        }
    }
    __syncthreads();
    if (m2 > 0) {
        float inv = s_inv;
        float an = 0.f;
        for (int e = 0; e < m1; e++) {
            float we = sc[e];
            if (we != 0.f) {
                int s = cand[e] & 0xffff;
                an += we * g_node[(size_t)(base + s) * 256 + tid];
            }
        }
        g_agg[(size_t)row * 256 + tid] = an * inv;
    }
}

// ---------------- GEMM1 (compacted rows): upd = agg @ W_gat[0:256] + epilogue ----
__global__ __launch_bounds__(256) void gemm1Kernel(
    const float* __restrict__ W, const float* __restrict__ bias)
{
    int nact = g_nact;
    int bc = blockIdx.x, br = blockIdx.y;
    if (br * 128 >= nact) return;
    int nrows = nact - br * 128;
    if (nrows > 128) nrows = 128;

    __shared__ __align__(16) float As[8][128];
    __shared__ __align__(16) float Bs[8][128];
    __shared__ int rows[128];
    int tid = threadIdx.x;
    if (tid < 128) rows[tid] = g_rows[br * 128 + (tid < nrows ? tid : nrows - 1)];
    __syncthreads();

    int aRow = tid >> 1, aCol = (tid & 1) * 4;
    int bRow = tid >> 5, bCol = (tid & 31) * 4;
    const float* Aptr = g_agg + (size_t)rows[aRow] * 256 + aCol;
    const float* Bptr = W + (size_t)bRow * 256 + bc * 128 + bCol;

    u64 acc2[4][8];
#pragma unroll
    for (int i = 0; i < 4; i++)
#pragma unroll
        for (int jj = 0; jj < 8; jj++) acc2[i][jj] = 0ull;

    int trow = (tid >> 4) * 8;
    int tcol = (tid & 15) * 8;

    for (int k0 = 0; k0 < 256; k0 += 8) {
        float4 av = *(const float4*)(Aptr + k0);
        As[aCol + 0][aRow] = av.x;
        As[aCol + 1][aRow] = av.y;
        As[aCol + 2][aRow] = av.z;
        As[aCol + 3][aRow] = av.w;
        float4 bv = *(const float4*)(Bptr + (size_t)k0 * 256);
        *(float4*)&Bs[bRow][bCol] = bv;
        __syncthreads();
#pragma unroll
        for (int k = 0; k < 8; k++) {
            const u64* a64 = (const u64*)&As[k][trow];
            u64 a2[4] = { a64[0], a64[1], a64[2], a64[3] };
            float bb[8];
            *(float4*)&bb[0] = *(const float4*)&Bs[k][tcol];
            *(float4*)&bb[4] = *(const float4*)&Bs[k][tcol + 4];
            u64 b2[8];
#pragma unroll
            for (int jj = 0; jj < 8; jj++) b2[jj] = bcast2(bb[jj]);
#pragma unroll
            for (int i = 0; i < 4; i++)
#pragma unroll
                for (int jj = 0; jj < 8; jj++) ffma2(acc2[i][jj], a2[i], b2[jj]);
        }
        __syncthreads();
    }

#pragma unroll
    for (int i2 = 0; i2 < 4; i2++) {
#pragma unroll
        for (int half = 0; half < 2; half++) {
            int idx = trow + 2 * i2 + half;
            if (idx >= nrows) continue;
            int r = rows[idx];
            float w0 = g_w0[r], w1 = g_w1[r];
#pragma unroll
            for (int jj = 0; jj < 8; jj++) {
                float2 v = unpk2(acc2[i2][jj]);
                float val = half ? v.y : v.x;
                int c = bc * 128 + tcol + jj;
                float u = val + bias[c] + w0 * g_E[0][c] + w1 * g_E[1][c];
                g_add[(size_t)r * 256 + c] = fmaxf(u, 0.f);
            }
        }
    }
}

// ---------------- deterministic scatter-add into output ----------------------
__global__ __launch_bounds__(256) void scatterKernel(
    float* __restrict__ out,
    const int* __restrict__ asp_st, const int* __restrict__ opi_st)
{
    int b = blockIdx.x >> 7;
    int c = blockIdx.x & 127;
    int h = threadIdx.x;
    if (!g_bhas[b]) return;      // whole batch contributes zero
    __shared__ int cen[512];
    __shared__ int hns[512];
    for (int i = h; i < 512; i += 256) {
        cen[i] = (asp_st[b * Nc + i] + opi_st[b * Nc + i]) >> 1;
        hns[i] = g_hn[b * Nc + i];
    }
    __syncthreads();
    float s = 0.f;
    bool any = false;
    for (int n = 0; n < 512; n++) {
        if (cen[n] == c) {
            size_t o = ((size_t)(b * Nc + n)) * 256 + h;
            s += hns[n] ? g_add[o] : g_node[o];
            any = true;
        }
    }
    if (any) out[((size_t)b * Lc + c) * Hc + h] += s;
}

// ---------------- launch -----------------------------------------------------
extern "C" void kernel_launch(void* const* d_in, const int* in_sizes, int n_in,
                              void* d_out, int out_size)
{
    const float* emb     = (const float*)d_in[0];
    const float* W_trip  = (const float*)d_in[1];
    const float* b_trip  = (const float*)d_in[2];
    const float* edge_e  = (const float*)d_in[3];
    const float* W_attn  = (const float*)d_in[4];
    const float* b_attn  = (const float*)d_in[5];
    const float* W_gat   = (const float*)d_in[6];
    const float* b_gat   = (const float*)d_in[7];
    const int*   asp_st  = (const int*)d_in[8];
    const int*   asp_len = (const int*)d_in[9];
    const int*   opi_st  = (const int*)d_in[10];
    const int*   opi_len = (const int*)d_in[11];
    const int*   sent_id = (const int*)d_in[12];
    float* out = (float*)d_out;

    cudaMemcpyAsync(out, emb, (size_t)Bc * Lc * Hc * sizeof(float),
                    cudaMemcpyDeviceToDevice, 0);

    gemm0Kernel<<<dim3(4, 34), 256>>>(emb, W_trip);
    buildKernel<<<Bc, 512>>>(asp_st, asp_len, opi_st, opi_len, edge_e, W_attn, W_gat);
    nodeStatsKernel<<<NROWS, 256>>>(asp_st, asp_len, opi_st, opi_len, sent_id,
                                    W_trip, b_trip, W_attn);
    edgeKernel<<<NROWS, 256>>>(b_attn);
    gemm1Kernel<<<dim3(2, 128), 256>>>(W_gat, b_gat);
    scatterKernel<<<Bc * 128, 256>>>(out, asp_st, opi_st);
}

// round 4
// speedup vs baseline: 2.1752x; 1.6884x over previous
#include <cuda_runtime.h>
#include <cstdint>

#define Bc 32
#define Lc 4096
#define Hc 256
#define Nc 512
#define NROWS (Bc * Nc)          // 16384
#define TT 136                   // tokens reachable by spans
#define PROWS (Bc * TT)          // 4352
#define SLOPE 0.2f
#define NEGINF (-3.4028234663852886e38f)
#define EDGECAP (Nc * (Nc - 1) * 2)
#define WCAP 256                 // per-row candidate cap in edge phase

// copy partition: 8,388,608 float4 total = 2048 blocks x 4096 float4
#define CPY_A 768
#define CPY_B 768
#define CPY_C 512

typedef unsigned long long u64;

// ---------------- scratch ----------------
__device__ __align__(16) float g_Y[(size_t)PROWS * 512];
__device__ __align__(16) float g_node[(size_t)NROWS * 256];
__device__ __align__(16) float g_agg[(size_t)NROWS * 256];
__device__ __align__(16) float g_add[(size_t)NROWS * 256];
__device__ float g_AT[NROWS];
__device__ float g_AS[NROWS];
__device__ float g_AE[2];
__device__ float g_E[2][256];
__device__ float g_w0[NROWS];
__device__ float g_w1[NROWS];
__device__ int   g_hn[NROWS];
__device__ int   g_bhas[Bc];
__device__ int   g_rowcnt[NROWS];
__device__ int   g_rowoff[NROWS];
__device__ int   g_cand[(size_t)Bc * EDGECAP];
__device__ int   g_rows[NROWS];
__device__ int   g_nact;
__device__ int   g_clist[(size_t)Bc * 128 * 512];   // per-(b,center) row lists
__device__ int   g_ccnt[Bc * 128];

// ---------------- f32x2 helpers ----------------
__device__ __forceinline__ u64 bcast2(float x) {
    u64 r; unsigned xi = __float_as_uint(x);
    asm("mov.b64 %0, {%1, %1};" : "=l"(r) : "r"(xi));
    return r;
}
__device__ __forceinline__ void ffma2(u64& d, u64 a, u64 b) {
    asm("fma.rn.f32x2 %0, %1, %2, %0;" : "+l"(d) : "l"(a), "l"(b));
}
__device__ __forceinline__ float2 unpk2(u64 v) {
    float2 r;
    asm("mov.b64 {%0, %1}, %2;" : "=f"(r.x), "=f"(r.y) : "l"(v));
    return r;
}

// ---------------- embedded copy block: 4096 float4 per block ----------------
__device__ __forceinline__ void copyBlk(float4* __restrict__ dst,
                                        const float4* __restrict__ src,
                                        int cblk, int tid)
{
    size_t base = ((size_t)cblk << 12) + tid;
#pragma unroll
    for (int i = 0; i < 16; i++) dst[base + (i << 8)] = src[base + (i << 8)];
}

// =================================================================================
// L1: gemm0 (blocks 0..135) + build (136..167) + copyA (168..168+CPY_A)
// =================================================================================
__global__ __launch_bounds__(256) void mega0Kernel(
    float* __restrict__ out, const float* __restrict__ emb,
    const float* __restrict__ W_trip,
    const int* __restrict__ asp_st, const int* __restrict__ asp_len,
    const int* __restrict__ opi_st, const int* __restrict__ opi_len,
    const float* __restrict__ edge_emb, const float* __restrict__ W_attn,
    const float* __restrict__ W_gat)
{
    int blk = blockIdx.x, tid = threadIdx.x;

    if (blk >= 168) {   // ---- copy chunk A ----
        copyBlk((float4*)out, (const float4*)emb, blk - 168, tid);
        return;
    }

    if (blk < 136) {    // ---- gemm0: Y = emb_tok[4352,256] @ Wcat[256,512] ----
        __shared__ __align__(16) float As[8][128];
        __shared__ __align__(16) float Bs[8][128];
        int bc = blk & 3, br = blk >> 2;
        int aRow = tid >> 1, aCol = (tid & 1) * 4;
        int bRow = tid >> 5, bCol = (tid & 31) * 4;

        int r = br * 128 + aRow;
        int b = r / TT;
        int t = r - b * TT;
        const float* Aptr = emb + ((size_t)(b * Lc + t)) * 256 + aCol;
        int j = bc * 128 + bCol;
        int half = (j >= 256);
        const float* Bptr = W_trip + (size_t)(half * 256 + bRow) * 256 + (j & 255);

        u64 acc2[4][8];
#pragma unroll
        for (int i = 0; i < 4; i++)
#pragma unroll
            for (int jj = 0; jj < 8; jj++) acc2[i][jj] = 0ull;

        int trow = (tid >> 4) * 8;
        int tcol = (tid & 15) * 8;

        for (int k0 = 0; k0 < 256; k0 += 8) {
            float4 av = *(const float4*)(Aptr + k0);
            As[aCol + 0][aRow] = av.x;
            As[aCol + 1][aRow] = av.y;
            As[aCol + 2][aRow] = av.z;
            As[aCol + 3][aRow] = av.w;
            float4 bv = *(const float4*)(Bptr + (size_t)k0 * 256);
            *(float4*)&Bs[bRow][bCol] = bv;
            __syncthreads();
#pragma unroll
            for (int k = 0; k < 8; k++) {
                const u64* a64 = (const u64*)&As[k][trow];
                u64 a2[4] = { a64[0], a64[1], a64[2], a64[3] };
                float bb[8];
                *(float4*)&bb[0] = *(const float4*)&Bs[k][tcol];
                *(float4*)&bb[4] = *(const float4*)&Bs[k][tcol + 4];
                u64 b2[8];
#pragma unroll
                for (int jj = 0; jj < 8; jj++) b2[jj] = bcast2(bb[jj]);
#pragma unroll
                for (int i = 0; i < 4; i++)
#pragma unroll
                    for (int jj = 0; jj < 8; jj++) ffma2(acc2[i][jj], a2[i], b2[jj]);
            }
            __syncthreads();
        }
#pragma unroll
        for (int i2 = 0; i2 < 4; i2++) {
            int r0 = br * 128 + trow + 2 * i2;
#pragma unroll
            for (int jj = 0; jj < 8; jj++) {
                float2 v = unpk2(acc2[i2][jj]);
                int c = bc * 128 + tcol + jj;
                g_Y[(size_t)r0 * 512 + c]       = v.x;
                g_Y[(size_t)(r0 + 1) * 512 + c] = v.y;
            }
        }
        return;
    }

    // ---- build: per-batch CSR + center lists + misc scalars ----
    {
        int bb = blk - 136;
        int base = bb * Nc;
        __shared__ int ka[512], ko[512], cen[512];
        __shared__ int wsum[8];
        __shared__ int sc_cnt[128];
        for (int i = tid; i < 512; i += 256) {
            int st = asp_st[base + i], ln = asp_len[base + i];
            int so = opi_st[base + i], lo = opi_len[base + i];
            ka[i] = st | (ln << 16);
            ko[i] = so | (lo << 16);
            cen[i] = (st + so) >> 1;
        }
        if (tid < 128) sc_cnt[tid] = 0;
        __syncthreads();

        int t0 = 2 * tid, t1 = t0 + 1;
        int ka0 = ka[t0], ko0 = ko[t0], ce0 = cen[t0];
        int ka1 = ka[t1], ko1 = ko[t1], ce1 = cen[t1];
        int c0 = 0, c1 = 0, r0 = 0, r1 = 0;
        for (int s = 0; s < 512; s++) {
            int kas = ka[s], kos = ko[s], ces = cen[s];
            if (s != t0) c0 += (kas == ka0) + (kos == ko0);
            if (s != t1) c1 += (kas == ka1) + (kos == ko1);
            r0 += (s < t0 && ces == ce0);
            r1 += (s < t1 && ces == ce1);
        }
        int ps = c0 + c1;
        int lane = tid & 31, w = tid >> 5;
        int v = ps;
#pragma unroll
        for (int o = 1; o < 32; o <<= 1) {
            int n = __shfl_up_sync(0xffffffffu, v, o);
            if (lane >= o) v += n;
        }
        if (lane == 31) wsum[w] = v;
        __syncthreads();
        if (tid == 0) {
            int run = 0;
#pragma unroll
            for (int i = 0; i < 8; i++) { int x = wsum[i]; wsum[i] = run; run += x; }
        }
        __syncthreads();
        int off = v - ps + wsum[w];
        g_rowcnt[base + t0] = c0;
        g_rowcnt[base + t1] = c1;
        int p0 = bb * EDGECAP + off;
        int p1 = p0 + c0;
        g_rowoff[base + t0] = p0;
        g_rowoff[base + t1] = p1;
        for (int s = 0; s < 512; s++) {
            int kas = ka[s], kos = ko[s];
            if (s != t0) {
                if (kas == ka0) g_cand[p0++] = s;
                if (kos == ko0) g_cand[p0++] = s | (1 << 16);
            }
            if (s != t1) {
                if (kas == ka1) g_cand[p1++] = s;
                if (kos == ko1) g_cand[p1++] = s | (1 << 16);
            }
        }
        g_clist[((size_t)(bb * 128 + ce0) << 9) + r0] = t0;
        g_clist[((size_t)(bb * 128 + ce1) << 9) + r1] = t1;
        atomicAdd(&sc_cnt[ce0], 1);
        atomicAdd(&sc_cnt[ce1], 1);
        __syncthreads();
        if (tid < 128) g_ccnt[bb * 128 + tid] = sc_cnt[tid];

        if (bb == 0) {
            // g_E[e][h] = edge_emb[e] @ W_gat[256:512]
            int h = tid;
#pragma unroll
            for (int e = 0; e < 2; e++) {
                float s = 0.f;
                for (int k = 0; k < 256; k++)
                    s += edge_emb[e * 256 + k] * W_gat[(size_t)(256 + k) * 256 + h];
                g_E[e][h] = s;
            }
            if (tid < 2) {
                float sa = 0.f;
                for (int k = 0; k < 256; k++) {
                    float vv = edge_emb[tid * 256 + k];
                    vv = (vv >= 0.f) ? vv : SLOPE * vv;
                    sa += vv * W_attn[512 + k];
                }
                g_AE[tid] = sa;
            }
            if (tid >= 4 && tid < 4 + Bc) g_bhas[tid - 4] = 0;
            if (tid == 2) g_nact = 0;
        }
    }
}

// =================================================================================
// L2: nodeStats (blocks 0..8191, 2 rows/block, float2) + copyB
// =================================================================================
__global__ __launch_bounds__(256) void nodeStatsKernel(
    float* __restrict__ out, const float* __restrict__ emb,
    const int* __restrict__ asp_st, const int* __restrict__ asp_len,
    const int* __restrict__ opi_st, const int* __restrict__ opi_len,
    const int* __restrict__ sent, const float* __restrict__ W_trip,
    const float* __restrict__ b_trip, const float* __restrict__ W_attn)
{
    int blk = blockIdx.x, tid = threadIdx.x;
    if (blk >= 8192) {
        copyBlk((float4*)out, (const float4*)emb, CPY_A + (blk - 8192), tid);
        return;
    }
    int half = tid >> 7;
    int hh = tid & 127;            // float2 column index
    int row = blk * 2 + half;
    int b = row >> 9;
    const float2* Yb = (const float2*)(g_Y + (size_t)b * TT * 512);

    int ast = asp_st[row], aln = asp_len[row];
    int ost = opi_st[row], oln = opi_len[row];

    float2 asum = make_float2(0.f, 0.f);
#pragma unroll 4
    for (int k = 0; k <= aln; k++) {
        float2 v = Yb[(size_t)(ast + k) * 256 + hh];
        asum.x += v.x; asum.y += v.y;
    }
    float2 osum = make_float2(0.f, 0.f);
#pragma unroll 4
    for (int k = 0; k <= oln; k++) {
        float2 v = Yb[(size_t)(ost + k) * 256 + 128 + hh];
        osum.x += v.x; osum.y += v.y;
    }
    float ia = 1.f / (float)(aln + 1), io = 1.f / (float)(oln + 1);
    int sid = sent[row];
    float2 wt = ((const float2*)W_trip)[(size_t)(512 + sid) * 128 + hh];
    float2 bt = ((const float2*)b_trip)[hh];
    float2 v2;
    v2.x = asum.x * ia + osum.x * io + wt.x + bt.x;
    v2.y = asum.y * ia + osum.y * io + wt.y + bt.y;
    ((float2*)g_node)[((size_t)row << 7) + hh] = v2;

    float lx = (v2.x >= 0.f) ? v2.x : SLOPE * v2.x;
    float ly = (v2.y >= 0.f) ? v2.y : SLOPE * v2.y;
    float2 wa_t = ((const float2*)W_attn)[hh];
    float2 wa_s = ((const float2*)W_attn)[128 + hh];
    float at = lx * wa_t.x + ly * wa_t.y;
    float as = lx * wa_s.x + ly * wa_s.y;
#pragma unroll
    for (int o = 16; o; o >>= 1) {
        at += __shfl_xor_sync(0xffffffffu, at, o);
        as += __shfl_xor_sync(0xffffffffu, as, o);
    }
    __shared__ float sAt[8], sAs[8];
    int w = tid >> 5;
    if ((tid & 31) == 0) { sAt[w] = at; sAs[w] = as; }
    __syncthreads();
    if (hh == 0) {
        int w0 = half * 4;
        float a = sAt[w0] + sAt[w0 + 1] + sAt[w0 + 2] + sAt[w0 + 3];
        float s2 = sAs[w0] + sAs[w0 + 1] + sAs[w0 + 2] + sAs[w0 + 3];
        g_AT[row] = a;
        g_AS[row] = s2;
    }
}

// =================================================================================
// L3: edge (warp-per-row, blocks 0..2047) + copyC
// =================================================================================
__global__ __launch_bounds__(256) void edgeKernel(
    float* __restrict__ out, const float* __restrict__ emb,
    const float* __restrict__ b_attn)
{
    int blk = blockIdx.x, tid = threadIdx.x;
    if (blk >= 2048) {
        copyBlk((float4*)out, (const float4*)emb, CPY_A + CPY_B + (blk - 2048), tid);
        return;
    }
    __shared__ int   s_cand[8][WCAP];
    __shared__ float s_sc[8][WCAP];
    int warp = tid >> 5, lane = tid & 31;
    int row = blk * 8 + warp;
    int b = row >> 9, bs = b * Nc;

    int m1 = g_rowcnt[row];
    if (m1 == 0) {
        if (lane == 0) g_hn[row] = 0;
        return;
    }
    if (m1 > WCAP) m1 = WCAP;
    int off = g_rowoff[row];
    for (int e = lane; e < m1; e += 32) s_cand[warp][e] = g_cand[off + e];

    const float* rp = g_node + ((size_t)row << 8);
    float nT[8];
#pragma unroll
    for (int k = 0; k < 8; k++) nT[k] = rp[lane + 32 * k];
    __syncwarp();

    float atv = g_AT[row], bat = b_attn[0];
    int m2 = 0;
    for (int e = 0; e < m1; e++) {
        int cd = s_cand[warp][e];
        int s = cd & 0xffff;
        const float* ns = g_node + ((size_t)(bs + s) << 8);
        float d = 0.f;
#pragma unroll
        for (int k = 0; k < 8; k++) d += nT[k] * ns[lane + 32 * k];
#pragma unroll
        for (int o = 16; o; o >>= 1) d += __shfl_xor_sync(0xffffffffu, d, o);
        if (lane == 0) {
            if (d > 0.f) { s_sc[warp][e] = atv + g_AS[bs + s] + g_AE[cd >> 16] + bat; m2++; }
            else s_sc[warp][e] = NEGINF;
        }
    }
    m2 = __shfl_sync(0xffffffffu, m2, 0);
    float invden = 0.f;
    if (lane == 0) {
        g_hn[row] = (m2 > 0) ? 1 : 0;
        if (m2 > 0) {
            atomicOr(&g_bhas[b], 1);
            int p = atomicAdd(&g_nact, 1);
            g_rows[p] = row;
            float mx = NEGINF;
            for (int e = 0; e < m1; e++) mx = fmaxf(mx, s_sc[warp][e]);
            float den = 0.f, w0 = 0.f, w1 = 0.f;
            for (int e = 0; e < m1; e++) {
                float we = expf(s_sc[warp][e] - mx);
                s_sc[warp][e] = we;
                den += we;
                if ((s_cand[warp][e] >> 16) == 0) w0 += we; else w1 += we;
            }
            invden = 1.f / den;
            g_w0[row] = w0 / den;
            g_w1[row] = w1 / den;
        }
    }
    invden = __shfl_sync(0xffffffffu, invden, 0);
    __syncwarp();
    if (m2 > 0) {
        float acc[8];
#pragma unroll
        for (int k = 0; k < 8; k++) acc[k] = 0.f;
        for (int e = 0; e < m1; e++) {
            float we = s_sc[warp][e];
            if (we != 0.f) {
                int s = s_cand[warp][e] & 0xffff;
                const float* ns = g_node + ((size_t)(bs + s) << 8);
#pragma unroll
                for (int k = 0; k < 8; k++) acc[k] += we * ns[lane + 32 * k];
            }
        }
        float* ag = g_agg + ((size_t)row << 8);
#pragma unroll
        for (int k = 0; k < 8; k++) ag[lane + 32 * k] = acc[k] * invden;
    }
}

// =================================================================================
// L4: GEMM1 on compacted active rows
// =================================================================================
__global__ __launch_bounds__(256) void gemm1Kernel(
    const float* __restrict__ W, const float* __restrict__ bias)
{
    int nact = g_nact;
    int bc = blockIdx.x, br = blockIdx.y;
    if (br * 128 >= nact) return;
    int nrows = nact - br * 128;
    if (nrows > 128) nrows = 128;

    __shared__ __align__(16) float As[8][128];
    __shared__ __align__(16) float Bs[8][128];
    __shared__ int rows[128];
    int tid = threadIdx.x;
    if (tid < 128) rows[tid] = g_rows[br * 128 + (tid < nrows ? tid : nrows - 1)];
    __syncthreads();

    int aRow = tid >> 1, aCol = (tid & 1) * 4;
    int bRow = tid >> 5, bCol = (tid & 31) * 4;
    const float* Aptr = g_agg + (size_t)rows[aRow] * 256 + aCol;
    const float* Bptr = W + (size_t)bRow * 256 + bc * 128 + bCol;

    u64 acc2[4][8];
#pragma unroll
    for (int i = 0; i < 4; i++)
#pragma unroll
        for (int jj = 0; jj < 8; jj++) acc2[i][jj] = 0ull;

    int trow = (tid >> 4) * 8;
    int tcol = (tid & 15) * 8;

    for (int k0 = 0; k0 < 256; k0 += 8) {
        float4 av = *(const float4*)(Aptr + k0);
        As[aCol + 0][aRow] = av.x;
        As[aCol + 1][aRow] = av.y;
        As[aCol + 2][aRow] = av.z;
        As[aCol + 3][aRow] = av.w;
        float4 bv = *(const float4*)(Bptr + (size_t)k0 * 256);
        *(float4*)&Bs[bRow][bCol] = bv;
        __syncthreads();
#pragma unroll
        for (int k = 0; k < 8; k++) {
            const u64* a64 = (const u64*)&As[k][trow];
            u64 a2[4] = { a64[0], a64[1], a64[2], a64[3] };
            float bb[8];
            *(float4*)&bb[0] = *(const float4*)&Bs[k][tcol];
            *(float4*)&bb[4] = *(const float4*)&Bs[k][tcol + 4];
            u64 b2[8];
#pragma unroll
            for (int jj = 0; jj < 8; jj++) b2[jj] = bcast2(bb[jj]);
#pragma unroll
            for (int i = 0; i < 4; i++)
#pragma unroll
                for (int jj = 0; jj < 8; jj++) ffma2(acc2[i][jj], a2[i], b2[jj]);
        }
        __syncthreads();
    }

#pragma unroll
    for (int i2 = 0; i2 < 4; i2++) {
#pragma unroll
        for (int half = 0; half < 2; half++) {
            int idx = trow + 2 * i2 + half;
            if (idx >= nrows) continue;
            int r = rows[idx];
            float w0 = g_w0[r], w1 = g_w1[r];
#pragma unroll
            for (int jj = 0; jj < 8; jj++) {
                float2 v = unpk2(acc2[i2][jj]);
                float val = half ? v.y : v.x;
                int c = bc * 128 + tcol + jj;
                float u = val + bias[c] + w0 * g_E[0][c] + w1 * g_E[1][c];
                g_add[(size_t)r * 256 + c] = fmaxf(u, 0.f);
            }
        }
    }
}

// =================================================================================
// L5: scatter via precomputed center lists
// =================================================================================
__global__ __launch_bounds__(256) void scatterKernel(float* __restrict__ out)
{
    int b = blockIdx.x >> 7;
    int c = blockIdx.x & 127;
    int h = threadIdx.x;
    if (!g_bhas[b]) return;
    int cnt = g_ccnt[b * 128 + c];
    if (cnt == 0) return;
    const int* list = g_clist + ((size_t)(b * 128 + c) << 9);
    float s = 0.f;
    for (int i = 0; i < cnt; i++) {
        int r = b * Nc + list[i];
        size_t o = ((size_t)r << 8) + h;
        s += g_hn[r] ? g_add[o] : g_node[o];
    }
    out[((size_t)b * Lc + c) * Hc + h] += s;
}

// ---------------- launch -----------------------------------------------------
extern "C" void kernel_launch(void* const* d_in, const int* in_sizes, int n_in,
                              void* d_out, int out_size)
{
    const float* emb     = (const float*)d_in[0];
    const float* W_trip  = (const float*)d_in[1];
    const float* b_trip  = (const float*)d_in[2];
    const float* edge_e  = (const float*)d_in[3];
    const float* W_attn  = (const float*)d_in[4];
    const float* b_attn  = (const float*)d_in[5];
    const float* W_gat   = (const float*)d_in[6];
    const float* b_gat   = (const float*)d_in[7];
    const int*   asp_st  = (const int*)d_in[8];
    const int*   asp_len = (const int*)d_in[9];
    const int*   opi_st  = (const int*)d_in[10];
    const int*   opi_len = (const int*)d_in[11];
    const int*   sent_id = (const int*)d_in[12];
    float* out = (float*)d_out;

    mega0Kernel<<<168 + CPY_A, 256>>>(out, emb, W_trip, asp_st, asp_len,
                                      opi_st, opi_len, edge_e, W_attn, W_gat);
    nodeStatsKernel<<<8192 + CPY_B, 256>>>(out, emb, asp_st, asp_len, opi_st, opi_len,
                                           sent_id, W_trip, b_trip, W_attn);
    edgeKernel<<<2048 + CPY_C, 256>>>(out, emb, b_attn);
    gemm1Kernel<<<dim3(2, 128), 256>>>(W_gat, b_gat);
    scatterKernel<<<Bc * 128, 256>>>(out);
}